// round 7
// baseline (speedup 1.0000x reference)
#include <cuda_runtime.h>
#include <cuda_bf16.h>
#include <math.h>
#include <stdint.h>

#define NN 4
#define LL 4096
#define HH 16
#define DD 64
#define MM 64
#define CC 128
#define GG 32
#define EPSF 1e-6f

typedef unsigned int u32;

static __device__ float g_kv[(size_t)NN * GG * HH * MM * DD];
static __device__ float g_ksum[(size_t)NN * GG * HH * DD];

__device__ __forceinline__ float phi(float x) { return x > 0.f ? x + 1.f : __expf(x); }

__device__ __forceinline__ void split2(float x0, float x1, u32& h, u32& l) {
    asm("cvt.rn.bf16x2.f32 %0, %1, %2;" : "=r"(h) : "f"(x1), "f"(x0));
    float f0 = __uint_as_float(h << 16);
    float f1 = __uint_as_float(h & 0xFFFF0000u);
    asm("cvt.rn.bf16x2.f32 %0, %1, %2;" : "=r"(l) : "f"(x1 - f1), "f"(x0 - f0));
}
__device__ __forceinline__ float bflo(u32 u) { return __uint_as_float(u << 16); }
__device__ __forceinline__ float bfhi(u32 u) { return __uint_as_float(u & 0xFFFF0000u); }

__device__ __forceinline__ u32 smem_u32(const void* p) {
    u32 a;
    asm("{ .reg .u64 t; cvta.to.shared.u64 t, %1; cvt.u32.u64 %0, t; }" : "=r"(a) : "l"(p));
    return a;
}
__device__ __forceinline__ void ldm4(u32& r0, u32& r1, u32& r2, u32& r3, u32 a) {
    asm volatile("ldmatrix.sync.aligned.m8n8.x4.shared.b16 {%0,%1,%2,%3},[%4];"
                 : "=r"(r0), "=r"(r1), "=r"(r2), "=r"(r3) : "r"(a));
}
__device__ __forceinline__ void ldm2(u32& r0, u32& r1, u32 a) {
    asm volatile("ldmatrix.sync.aligned.m8n8.x2.shared.b16 {%0,%1},[%2];"
                 : "=r"(r0), "=r"(r1) : "r"(a));
}
// NOTE: non-volatile — pure register op; lets the compiler interleave
// independent accumulator chains (the R6 profile showed issue=26%).
__device__ __forceinline__ void mma16816(float* d, u32 a0, u32 a1, u32 a2, u32 a3,
                                         u32 b0, u32 b1) {
    asm("mma.sync.aligned.m16n8k16.row.col.f32.bf16.bf16.f32 "
        "{%0,%1,%2,%3},{%4,%5,%6,%7},{%8,%9},{%0,%1,%2,%3};"
        : "+f"(d[0]), "+f"(d[1]), "+f"(d[2]), "+f"(d[3])
        : "r"(a0), "r"(a1), "r"(a2), "r"(a3), "r"(b0), "r"(b1));
}
__device__ __forceinline__ u32 off128(int row, int kb) {
    return (u32)(row * 128) + (u32)(((((kb >> 4) & 7) ^ (row & 7)) << 4) | (kb & 15));
}
__device__ __forceinline__ u32 off256(int row, int kb) {
    return (u32)(row * 256) + (u32)(kb & 128)
         + (u32)(((((kb >> 4) & 7) ^ (row & 7)) << 4) | (kb & 15));
}

// ---------------------------------------------------------------------------
// Kernel A: kvT[m][d] = sum_c v[c][m] * phi(k)[c][d]  (mma bf16x3)
// ---------------------------------------------------------------------------
__global__ void __launch_bounds__(256, 3) chunk_state_kernel(
    const float* __restrict__ k, const float* __restrict__ v)
{
    extern __shared__ char sm_[];
    const int VTH = 0, VTL = 16384, KTH = 32768, KTL = 49152;
    u32 sb = smem_u32(sm_);

    int tid = threadIdx.x, lane = tid & 31, wid = tid >> 5;
    int bid = blockIdx.x;
    int h = bid % HH;
    int gc = (bid / HH) % GG;
    int n = bid / (HH * GG);
    size_t base = (((size_t)n * LL + (size_t)gc * CC) * HH + h) * DD;

    int e0 = (tid & 15) * 4;
#pragma unroll
    for (int it = 0; it < 4; it++) {
        int cp = it * 16 + (tid >> 4);
        size_t off0 = base + (size_t)(cp * 2) * (HH * DD) + e0;
        float4 ka = *(const float4*)(k + off0);
        float4 kb = *(const float4*)(k + off0 + HH * DD);
        float4 va = *(const float4*)(v + off0);
        float4 vb = *(const float4*)(v + off0 + HH * DD);
        float fka[4] = { phi(ka.x), phi(ka.y), phi(ka.z), phi(ka.w) };
        float fkb[4] = { phi(kb.x), phi(kb.y), phi(kb.z), phi(kb.w) };
        float fva[4] = { va.x, va.y, va.z, va.w };
        float fvb[4] = { vb.x, vb.y, vb.z, vb.w };
#pragma unroll
        for (int t = 0; t < 4; t++) {
            u32 hh, ll;
            u32 ob = off256(e0 + t, cp * 4);
            split2(fka[t], fkb[t], hh, ll);
            *(u32*)(sm_ + KTH + ob) = hh;
            *(u32*)(sm_ + KTL + ob) = ll;
            split2(fva[t], fvb[t], hh, ll);
            *(u32*)(sm_ + VTH + ob) = hh;
            *(u32*)(sm_ + VTL + ob) = ll;
        }
    }
    __syncthreads();

    int grp = lane >> 2, tg = lane & 3;
    int m0 = (wid >> 1) * 16, n0 = (wid & 1) * 32;
    int rA = m0 + ((lane >> 3) & 1) * 8 + (lane & 7);
    int rB = (lane >> 4) * 8 + (lane & 7);
    int kbA0 = 16 * (lane >> 4);
    int kbB0 = 16 * ((lane >> 3) & 1);

    float acc[4][4] = {};
#pragma unroll
    for (int ks = 0; ks < 8; ks++) {
        u32 ah0, ah1, ah2, ah3, al0, al1, al2, al3;
        ldm4(ah0, ah1, ah2, ah3, sb + VTH + off256(rA, 32 * ks + kbA0));
        ldm4(al0, al1, al2, al3, sb + VTL + off256(rA, 32 * ks + kbA0));
#pragma unroll
        for (int jb = 0; jb < 2; jb++) {
            u32 b0, b1, b2, b3;
            u32 obB = off256(n0 + jb * 16 + rB, 32 * ks + kbB0);
            ldm4(b0, b1, b2, b3, sb + KTH + obB);
            mma16816(acc[2 * jb],     ah0, ah1, ah2, ah3, b0, b1);
            mma16816(acc[2 * jb + 1], ah0, ah1, ah2, ah3, b2, b3);
            mma16816(acc[2 * jb],     al0, al1, al2, al3, b0, b1);
            mma16816(acc[2 * jb + 1], al0, al1, al2, al3, b2, b3);
            ldm4(b0, b1, b2, b3, sb + KTL + obB);
            mma16816(acc[2 * jb],     ah0, ah1, ah2, ah3, b0, b1);
            mma16816(acc[2 * jb + 1], ah0, ah1, ah2, ah3, b2, b3);
        }
    }

    float* kvout = g_kv + (size_t)bid * (MM * DD);
#pragma unroll
    for (int j = 0; j < 4; j++) {
        int dc = n0 + (j >> 1) * 16 + (j & 1) * 8 + tg * 2;
        *(float2*)(kvout + (size_t)(m0 + grp) * DD + dc)     = make_float2(acc[j][0], acc[j][1]);
        *(float2*)(kvout + (size_t)(m0 + grp + 8) * DD + dc) = make_float2(acc[j][2], acc[j][3]);
    }

    if (tid < DD) {
        float s = 0.f;
#pragma unroll 8
        for (int j = 0; j < 64; j++) {
            int cu = (j + (tid >> 3) * 8) & 63;
            u32 ob = off256(tid, cu * 4);
            u32 uh = *(const u32*)(sm_ + KTH + ob);
            u32 ul = *(const u32*)(sm_ + KTL + ob);
            s += bflo(uh) + bfhi(uh) + bflo(ul) + bfhi(ul);
        }
        g_ksum[(size_t)bid * DD + tid] = s;
    }
}

// ---------------------------------------------------------------------------
// Kernel B: exclusive prefix over chunks, grid=256
// ---------------------------------------------------------------------------
__global__ void __launch_bounds__(256) prefix_kernel()
{
    int nh = blockIdx.x >> 2, qtr = blockIdx.x & 3;
    int n = nh / HH, h = nh % HH;
    int p4 = qtr * 256 + threadIdx.x;
    float4 run = make_float4(0.f, 0.f, 0.f, 0.f);
    for (int g = 0; g < GG; g++) {
        float4* p = (float4*)(g_kv + (((size_t)(n * GG + g) * HH) + h) * (DD * MM)) + p4;
        float4 t = *p;
        *p = run;
        run.x += t.x; run.y += t.y; run.z += t.z; run.w += t.w;
    }
    if (qtr == 0 && threadIdx.x < DD / 4) {
        float4 rs = make_float4(0.f, 0.f, 0.f, 0.f);
        for (int g = 0; g < GG; g++) {
            float4* p = (float4*)(g_ksum + (((size_t)(n * GG + g) * HH) + h) * DD) + threadIdx.x;
            float4 t = *p;
            *p = rs;
            rs.x += t.x; rs.y += t.y; rs.z += t.z; rs.w += t.w;
        }
    }
}

// ---------------------------------------------------------------------------
// Kernel C: register S, fused z, triangle-skip, inter-GEMM merged into GEMM1
// ---------------------------------------------------------------------------
#define QH 0
#define QL 16384
#define KH 32768
#define KL 49152
#define VH 65536
#define VL 83968
#define WH 102400
#define WL 111616
#define SMEM_C 120832

__global__ void __launch_bounds__(256) output_kernel(
    const float* __restrict__ q, const float* __restrict__ k,
    const float* __restrict__ v, float* __restrict__ out)
{
    extern __shared__ char sm_[];
    u32 sb = smem_u32(sm_);

    int tid = threadIdx.x, lane = tid & 31, wid = tid >> 5;
    int bid = blockIdx.x;
    int h = bid % HH;
    int gc = (bid / HH) % GG;
    int n = bid / (HH * GG);
    size_t base = (((size_t)n * LL + (size_t)gc * CC) * HH + h) * DD;

    // ---- loads ----
    for (int i = tid; i < CC * 16; i += 256) {
        int c = i >> 4, dq = (i & 15) << 2;
        size_t off = base + (size_t)c * (HH * DD) + dq;
        float4 q4 = *(const float4*)(q + off);
        float4 k4 = *(const float4*)(k + off);
        u32 h01, l01, h23, l23;
        u32 ob = off128(c, dq * 2);
        split2(phi(q4.x), phi(q4.y), h01, l01);
        split2(phi(q4.z), phi(q4.w), h23, l23);
        *(uint2*)(sm_ + QH + ob) = make_uint2(h01, h23);
        *(uint2*)(sm_ + QL + ob) = make_uint2(l01, l23);
        split2(phi(k4.x), phi(k4.y), h01, l01);
        split2(phi(k4.z), phi(k4.w), h23, l23);
        *(uint2*)(sm_ + KH + ob) = make_uint2(h01, h23);
        *(uint2*)(sm_ + KL + ob) = make_uint2(l01, l23);
    }
    {
        int e0 = (tid & 15) * 4;
#pragma unroll
        for (int it = 0; it < 4; it++) {
            int cp = it * 16 + (tid >> 4);
            size_t off0 = base + (size_t)(cp * 2) * (HH * DD) + e0;
            float4 va = *(const float4*)(v + off0);
            float4 vb = *(const float4*)(v + off0 + HH * DD);
            float fa[4] = { va.x, va.y, va.z, va.w };
            float fb[4] = { vb.x, vb.y, vb.z, vb.w };
#pragma unroll
            for (int t = 0; t < 4; t++) {
                u32 hh, ll;
                split2(fa[t], fb[t], hh, ll);
                u32 ob = off256(e0 + t, cp * 4);
                *(u32*)(sm_ + VH + ob) = hh;
                *(u32*)(sm_ + VL + ob) = ll;
            }
        }
    }
    {
        const float* kvp = g_kv + (size_t)bid * (MM * DD);
        for (int i = tid; i < DD * 16; i += 256) {
            int m = i >> 4, dq = (i & 15) << 2;
            float4 t4 = *(const float4*)(kvp + (size_t)m * DD + dq);
            u32 h01, l01, h23, l23;
            split2(t4.x, t4.y, h01, l01);
            split2(t4.z, t4.w, h23, l23);
            u32 ob = off128(m, dq * 2);
            *(uint2*)(sm_ + WH + ob) = make_uint2(h01, h23);
            *(uint2*)(sm_ + WL + ob) = make_uint2(l01, l23);
        }
    }
    if (tid < 16) {
        float4 t4 = *(const float4*)(g_ksum + (size_t)bid * DD + tid * 4);
        u32 h01, l01, h23, l23;
        split2(t4.x, t4.y, h01, l01);
        split2(t4.z, t4.w, h23, l23);
        u32 ob = off128(64, tid * 8);
        *(uint2*)(sm_ + WH + ob) = make_uint2(h01, h23);
        *(uint2*)(sm_ + WL + ob) = make_uint2(l01, l23);
    }
    for (int i = tid; i < 512; i += 256) {
        int row = 64 + (i >> 6), cu = i & 63;
        *(u32*)(sm_ + VH + row * 256 + cu * 4) = (row == 64) ? 0x3F803F80u : 0u;
        *(u32*)(sm_ + VL + row * 256 + cu * 4) = 0u;
    }
    if (tid < 224) {
        int row = 65 + (tid >> 5), cu = tid & 31;
        *(u32*)(sm_ + WH + row * 128 + cu * 4) = 0u;
        *(u32*)(sm_ + WL + row * 128 + cu * 4) = 0u;
    }
    __syncthreads();

    const int perm[8] = { 0, 7, 1, 6, 2, 5, 3, 4 };
    int wb = perm[wid];
    int m0 = wb * 16;
    int grp = lane >> 2, tg = lane & 3;
    int rA = m0 + ((lane >> 3) & 1) * 8 + (lane & 7);
    int rB = (lane >> 4) * 8 + (lane & 7);
    int kbA0 = 16 * (lane >> 4);
    int kbB0 = 16 * ((lane >> 3) & 1);
    int r9 = 64 + (lane & 7);

    // ---- fused GEMM1 (S = QK^T, tril cols only) + inter-GEMM (O += Q KV'^T) ----
    // Both share Q fragments and the ks loop; S-accs and O-accs are independent
    // chains, giving the scheduler ~16 parallel accumulators per iteration.
    float accS[16][4] = {};
    float accO[9][4] = {};
#pragma unroll
    for (int ks = 0; ks < 4; ks++) {
        u32 qh0, qh1, qh2, qh3, ql0, ql1, ql2, ql3;
        ldm4(qh0, qh1, qh2, qh3, sb + QH + off128(rA, 32 * ks + kbA0));
        ldm4(ql0, ql1, ql2, ql3, sb + QL + off128(rA, 32 * ks + kbA0));
        int kb = 32 * ks + kbB0;
        // --- S part: jb <= wb ---
#pragma unroll
        for (int jb = 0; jb < 8; jb++) {
            if (jb <= wb) {
                u32 b0, b1, b2, b3;
                u32 obB = off128(jb * 16 + rB, kb);
                ldm4(b0, b1, b2, b3, sb + KH + obB);
                mma16816(accS[2 * jb],     qh0, qh1, qh2, qh3, b0, b1);
                mma16816(accS[2 * jb + 1], qh0, qh1, qh2, qh3, b2, b3);
                mma16816(accS[2 * jb],     ql0, ql1, ql2, ql3, b0, b1);
                mma16816(accS[2 * jb + 1], ql0, ql1, ql2, ql3, b2, b3);
                ldm4(b0, b1, b2, b3, sb + KL + obB);
                mma16816(accS[2 * jb],     qh0, qh1, qh2, qh3, b0, b1);
                mma16816(accS[2 * jb + 1], qh0, qh1, qh2, qh3, b2, b3);
            }
        }
        // --- inter part: full N=72 ---
#pragma unroll
        for (int jb = 0; jb < 4; jb++) {
            u32 b0, b1, b2, b3;
            u32 obB = off128(jb * 16 + rB, kb);
            ldm4(b0, b1, b2, b3, sb + WH + obB);
            mma16816(accO[2 * jb],     qh0, qh1, qh2, qh3, b0, b1);
            mma16816(accO[2 * jb + 1], qh0, qh1, qh2, qh3, b2, b3);
            mma16816(accO[2 * jb],     ql0, ql1, ql2, ql3, b0, b1);
            mma16816(accO[2 * jb + 1], ql0, ql1, ql2, ql3, b2, b3);
            ldm4(b0, b1, b2, b3, sb + WL + obB);
            mma16816(accO[2 * jb],     qh0, qh1, qh2, qh3, b0, b1);
            mma16816(accO[2 * jb + 1], qh0, qh1, qh2, qh3, b2, b3);
        }
        u32 b0, b1;
        ldm2(b0, b1, sb + WH + off128(r9, kb));
        mma16816(accO[8], qh0, qh1, qh2, qh3, b0, b1);
        mma16816(accO[8], ql0, ql1, ql2, ql3, b0, b1);
        ldm2(b0, b1, sb + WL + off128(r9, kb));
        mma16816(accO[8], qh0, qh1, qh2, qh3, b0, b1);
    }

    // ---- mask tril + in-register split ----
    int r0 = m0 + grp, r1 = r0 + 8;
#pragma unroll
    for (int j = 0; j < 16; j++) {
        int c0 = j * 8 + tg * 2;
        if (c0 > r0)     accS[j][0] = 0.f;
        if (c0 + 1 > r0) accS[j][1] = 0.f;
        if (c0 > r1)     accS[j][2] = 0.f;
        if (c0 + 1 > r1) accS[j][3] = 0.f;
    }
    u32 Sh[8][4], Sl[8][4];
#pragma unroll
    for (int ks = 0; ks < 8; ks++) {
        split2(accS[2 * ks][0],     accS[2 * ks][1],     Sh[ks][0], Sl[ks][0]);
        split2(accS[2 * ks][2],     accS[2 * ks][3],     Sh[ks][1], Sl[ks][1]);
        split2(accS[2 * ks + 1][0], accS[2 * ks + 1][1], Sh[ks][2], Sl[ks][2]);
        split2(accS[2 * ks + 1][2], accS[2 * ks + 1][3], Sh[ks][3], Sl[ks][3]);
    }

    // ---- GEMM2 intra: ks <= wb only ----
#pragma unroll
    for (int ks = 0; ks < 8; ks++) {
        if (ks <= wb) {
            int kb = 32 * ks + kbB0;
#pragma unroll
            for (int jb = 0; jb < 4; jb++) {
                u32 b0, b1, b2, b3;
                u32 obB = off256(jb * 16 + rB, kb);
                ldm4(b0, b1, b2, b3, sb + VH + obB);
                mma16816(accO[2 * jb],     Sh[ks][0], Sh[ks][1], Sh[ks][2], Sh[ks][3], b0, b1);
                mma16816(accO[2 * jb + 1], Sh[ks][0], Sh[ks][1], Sh[ks][2], Sh[ks][3], b2, b3);
                mma16816(accO[2 * jb],     Sl[ks][0], Sl[ks][1], Sl[ks][2], Sl[ks][3], b0, b1);
                mma16816(accO[2 * jb + 1], Sl[ks][0], Sl[ks][1], Sl[ks][2], Sl[ks][3], b2, b3);
                ldm4(b0, b1, b2, b3, sb + VL + obB);
                mma16816(accO[2 * jb],     Sh[ks][0], Sh[ks][1], Sh[ks][2], Sh[ks][3], b0, b1);
                mma16816(accO[2 * jb + 1], Sh[ks][0], Sh[ks][1], Sh[ks][2], Sh[ks][3], b2, b3);
            }
            u32 b0, b1;
            ldm2(b0, b1, sb + VH + off256(r9, kb));
            mma16816(accO[8], Sh[ks][0], Sh[ks][1], Sh[ks][2], Sh[ks][3], b0, b1);
            mma16816(accO[8], Sl[ks][0], Sl[ks][1], Sl[ks][2], Sl[ks][3], b0, b1);
            ldm2(b0, b1, sb + VL + off256(r9, kb));
            mma16816(accO[8], Sh[ks][0], Sh[ks][1], Sh[ks][2], Sh[ks][3], b0, b1);
        }
    }

    // ---- normalize + store ----
    float zr0 = __shfl_sync(0xffffffffu, accO[8][0], lane & 28);
    float zr1 = __shfl_sync(0xffffffffu, accO[8][2], lane & 28);
    float rz0 = 1.0f / (zr0 + EPSF);
    float rz1 = 1.0f / (zr1 + EPSF);
    float* op0 = out + (((size_t)n * LL + (size_t)gc * CC + r0) * HH + h) * MM;
    float* op1 = op0 + (size_t)8 * HH * MM;
#pragma unroll
    for (int j = 0; j < 8; j++) {
        int c0 = j * 8 + tg * 2;
        *(float2*)(op0 + c0) = make_float2(accO[j][0] * rz0, accO[j][1] * rz0);
        *(float2*)(op1 + c0) = make_float2(accO[j][2] * rz1, accO[j][3] * rz1);
    }
}

// ---------------------------------------------------------------------------
extern "C" void kernel_launch(void* const* d_in, const int* in_sizes, int n_in,
                              void* d_out, int out_size)
{
    const float* q = (const float*)d_in[0];
    const float* k = (const float*)d_in[1];
    const float* v = (const float*)d_in[2];
    float* out = (float*)d_out;

    const int SMEM_A = 65536;

    cudaFuncSetAttribute(chunk_state_kernel,
                         cudaFuncAttributeMaxDynamicSharedMemorySize, SMEM_A);
    cudaFuncSetAttribute(output_kernel,
                         cudaFuncAttributeMaxDynamicSharedMemorySize, SMEM_C);

    chunk_state_kernel<<<NN * GG * HH, 256, SMEM_A>>>(k, v);
    prefix_kernel<<<NN * HH * 4, 256>>>();
    output_kernel<<<NN * GG * HH, 256, SMEM_C>>>(q, k, v, out);
}

// round 8
// speedup vs baseline: 1.6712x; 1.6712x over previous
#include <cuda_runtime.h>
#include <cuda_fp16.h>
#include <math.h>
#include <stdint.h>

#define NN 4
#define LL 4096
#define HH 16
#define DD 64
#define MM 64
#define CC 128
#define GG 32
#define EPSF 1e-6f

typedef unsigned int u32;

static __device__ float g_kv[(size_t)NN * GG * HH * MM * DD];
static __device__ float g_ksum[(size_t)NN * GG * HH * DD];

__device__ __forceinline__ float phi(float x) { return x > 0.f ? x + 1.f : __expf(x); }

// fp16 split: h = fp16(x), l = fp16(x - h).  A-side operands (2-pass scheme).
__device__ __forceinline__ void split2h(float x0, float x1, u32& h, u32& l) {
    __half2 hh = __floats2half2_rn(x0, x1);
    float2 f = __half22float2(hh);
    __half2 ll = __floats2half2_rn(x0 - f.x, x1 - f.y);
    h = *reinterpret_cast<u32*>(&hh);
    l = *reinterpret_cast<u32*>(&ll);
}
// fp16 round only: B-side operands.
__device__ __forceinline__ u32 rnd2h(float x0, float x1) {
    __half2 hh = __floats2half2_rn(x0, x1);
    return *reinterpret_cast<u32*>(&hh);
}

__device__ __forceinline__ u32 smem_u32(const void* p) {
    u32 a;
    asm("{ .reg .u64 t; cvta.to.shared.u64 t, %1; cvt.u32.u64 %0, t; }" : "=r"(a) : "l"(p));
    return a;
}
__device__ __forceinline__ void ldm4(u32& r0, u32& r1, u32& r2, u32& r3, u32 a) {
    asm volatile("ldmatrix.sync.aligned.m8n8.x4.shared.b16 {%0,%1,%2,%3},[%4];"
                 : "=r"(r0), "=r"(r1), "=r"(r2), "=r"(r3) : "r"(a));
}
__device__ __forceinline__ void ldm2(u32& r0, u32& r1, u32 a) {
    asm volatile("ldmatrix.sync.aligned.m8n8.x2.shared.b16 {%0,%1},[%2];"
                 : "=r"(r0), "=r"(r1) : "r"(a));
}
__device__ __forceinline__ void mma16816(float* d, u32 a0, u32 a1, u32 a2, u32 a3,
                                         u32 b0, u32 b1) {
    asm("mma.sync.aligned.m16n8k16.row.col.f32.f16.f16.f32 "
        "{%0,%1,%2,%3},{%4,%5,%6,%7},{%8,%9},{%0,%1,%2,%3};"
        : "+f"(d[0]), "+f"(d[1]), "+f"(d[2]), "+f"(d[3])
        : "r"(a0), "r"(a1), "r"(a2), "r"(a3), "r"(b0), "r"(b1));
}
__device__ __forceinline__ u32 off128(int row, int kb) {
    return (u32)(row * 128) + (u32)(((((kb >> 4) & 7) ^ (row & 7)) << 4) | (kb & 15));
}
__device__ __forceinline__ u32 off256(int row, int kb) {
    return (u32)(row * 256) + (u32)(kb & 128)
         + (u32)(((((kb >> 4) & 7) ^ (row & 7)) << 4) | (kb & 15));
}

// ---------------------------------------------------------------------------
// Kernel A: kvT[m][d] = sum_c v[c][m] * phi(k)[c][d]
// fp16 2-pass: V split (VTH/VTL), K rounded (KTH). smem = 48KB.
// ---------------------------------------------------------------------------
__global__ void __launch_bounds__(256, 3) chunk_state_kernel(
    const float* __restrict__ k, const float* __restrict__ v)
{
    extern __shared__ char sm_[];
    const int VTH = 0, VTL = 16384, KTH = 32768;
    u32 sb = smem_u32(sm_);

    int tid = threadIdx.x, lane = tid & 31, wid = tid >> 5;
    int bid = blockIdx.x;
    int h = bid % HH;
    int gc = (bid / HH) % GG;
    int n = bid / (HH * GG);
    size_t base = (((size_t)n * LL + (size_t)gc * CC) * HH + h) * DD;

    int e0 = (tid & 15) * 4;
#pragma unroll
    for (int it = 0; it < 4; it++) {
        int cp = it * 16 + (tid >> 4);
        size_t off0 = base + (size_t)(cp * 2) * (HH * DD) + e0;
        float4 ka = *(const float4*)(k + off0);
        float4 kb = *(const float4*)(k + off0 + HH * DD);
        float4 va = *(const float4*)(v + off0);
        float4 vb = *(const float4*)(v + off0 + HH * DD);
        float fka[4] = { phi(ka.x), phi(ka.y), phi(ka.z), phi(ka.w) };
        float fkb[4] = { phi(kb.x), phi(kb.y), phi(kb.z), phi(kb.w) };
        float fva[4] = { va.x, va.y, va.z, va.w };
        float fvb[4] = { vb.x, vb.y, vb.z, vb.w };
#pragma unroll
        for (int t = 0; t < 4; t++) {
            u32 ob = off256(e0 + t, cp * 4);
            *(u32*)(sm_ + KTH + ob) = rnd2h(fka[t], fkb[t]);
            u32 hh, ll;
            split2h(fva[t], fvb[t], hh, ll);
            *(u32*)(sm_ + VTH + ob) = hh;
            *(u32*)(sm_ + VTL + ob) = ll;
        }
    }
    __syncthreads();

    int grp = lane >> 2, tg = lane & 3;
    int m0 = (wid >> 1) * 16, n0 = (wid & 1) * 32;
    int rA = m0 + ((lane >> 3) & 1) * 8 + (lane & 7);
    int rB = (lane >> 4) * 8 + (lane & 7);
    int kbA0 = 16 * (lane >> 4);
    int kbB0 = 16 * ((lane >> 3) & 1);

    float acc[4][4] = {};
#pragma unroll
    for (int ks = 0; ks < 8; ks++) {
        u32 ah0, ah1, ah2, ah3, al0, al1, al2, al3;
        ldm4(ah0, ah1, ah2, ah3, sb + VTH + off256(rA, 32 * ks + kbA0));
        ldm4(al0, al1, al2, al3, sb + VTL + off256(rA, 32 * ks + kbA0));
#pragma unroll
        for (int jb = 0; jb < 2; jb++) {
            u32 b0, b1, b2, b3;
            ldm4(b0, b1, b2, b3, sb + KTH + off256(n0 + jb * 16 + rB, 32 * ks + kbB0));
            mma16816(acc[2 * jb],     ah0, ah1, ah2, ah3, b0, b1);
            mma16816(acc[2 * jb + 1], ah0, ah1, ah2, ah3, b2, b3);
            mma16816(acc[2 * jb],     al0, al1, al2, al3, b0, b1);
            mma16816(acc[2 * jb + 1], al0, al1, al2, al3, b2, b3);
        }
    }

    float* kvout = g_kv + (size_t)bid * (MM * DD);
#pragma unroll
    for (int j = 0; j < 4; j++) {
        int dc = n0 + (j >> 1) * 16 + (j & 1) * 8 + tg * 2;
        *(float2*)(kvout + (size_t)(m0 + grp) * DD + dc)     = make_float2(acc[j][0], acc[j][1]);
        *(float2*)(kvout + (size_t)(m0 + grp + 8) * DD + dc) = make_float2(acc[j][2], acc[j][3]);
    }

    if (tid < DD) {
        float s = 0.f;
#pragma unroll 8
        for (int j = 0; j < 64; j++) {
            int cu = (j + (tid >> 3) * 8) & 63;
            __half2 hh = *(const __half2*)(sm_ + KTH + off256(tid, cu * 4));
            float2 f = __half22float2(hh);
            s += f.x + f.y;
        }
        g_ksum[(size_t)bid * DD + tid] = s;
    }
}

// ---------------------------------------------------------------------------
// Kernel B: exclusive prefix over chunks, grid=256
// ---------------------------------------------------------------------------
__global__ void __launch_bounds__(256) prefix_kernel()
{
    int nh = blockIdx.x >> 2, qtr = blockIdx.x & 3;
    int n = nh / HH, h = nh % HH;
    int p4 = qtr * 256 + threadIdx.x;
    float4 run = make_float4(0.f, 0.f, 0.f, 0.f);
    for (int g = 0; g < GG; g++) {
        float4* p = (float4*)(g_kv + (((size_t)(n * GG + g) * HH) + h) * (DD * MM)) + p4;
        float4 t = *p;
        *p = run;
        run.x += t.x; run.y += t.y; run.z += t.z; run.w += t.w;
    }
    if (qtr == 0 && threadIdx.x < DD / 4) {
        float4 rs = make_float4(0.f, 0.f, 0.f, 0.f);
        for (int g = 0; g < GG; g++) {
            float4* p = (float4*)(g_ksum + (((size_t)(n * GG + g) * HH) + h) * DD) + threadIdx.x;
            float4 t = *p;
            *p = rs;
            rs.x += t.x; rs.y += t.y; rs.z += t.z; rs.w += t.w;
        }
    }
}

// ---------------------------------------------------------------------------
// Kernel C: fp16 2-pass, block-streamed S, fused z, triangle skip, 2 CTAs/SM.
// planes: QH 0, QL 16K, KH 32K (128 x 128B); VH 48K (72 x 256B: V^T + ones);
//         WH 66K (72 x 128B: KV^T + ksum).  total 75KB.
// ---------------------------------------------------------------------------
#define QHo 0
#define QLo 16384
#define KHo 32768
#define VHo 49152
#define WHo 67584
#define SMEM_C 76800

__global__ void __launch_bounds__(256, 2) output_kernel(
    const float* __restrict__ q, const float* __restrict__ k,
    const float* __restrict__ v, float* __restrict__ out)
{
    extern __shared__ char sm_[];
    u32 sb = smem_u32(sm_);

    int tid = threadIdx.x, lane = tid & 31, wid = tid >> 5;
    int bid = blockIdx.x;
    int h = bid % HH;
    int gc = (bid / HH) % GG;
    int n = bid / (HH * GG);
    size_t base = (((size_t)n * LL + (size_t)gc * CC) * HH + h) * DD;

    // ---- Q (split) and K (rounded) rows ----
    for (int i = tid; i < CC * 16; i += 256) {
        int c = i >> 4, dq = (i & 15) << 2;
        size_t off = base + (size_t)c * (HH * DD) + dq;
        float4 q4 = *(const float4*)(q + off);
        float4 k4 = *(const float4*)(k + off);
        u32 ob = off128(c, dq * 2);
        u32 h01, l01, h23, l23;
        split2h(phi(q4.x), phi(q4.y), h01, l01);
        split2h(phi(q4.z), phi(q4.w), h23, l23);
        *(uint2*)(sm_ + QHo + ob) = make_uint2(h01, h23);
        *(uint2*)(sm_ + QLo + ob) = make_uint2(l01, l23);
        *(uint2*)(sm_ + KHo + ob) =
            make_uint2(rnd2h(phi(k4.x), phi(k4.y)), rnd2h(phi(k4.z), phi(k4.w)));
    }
    // ---- V transposed (rounded) rows 0..63 ----
    {
        int e0 = (tid & 15) * 4;
#pragma unroll
        for (int it = 0; it < 4; it++) {
            int cp = it * 16 + (tid >> 4);
            size_t off0 = base + (size_t)(cp * 2) * (HH * DD) + e0;
            float4 va = *(const float4*)(v + off0);
            float4 vb = *(const float4*)(v + off0 + HH * DD);
            float fa[4] = { va.x, va.y, va.z, va.w };
            float fb[4] = { vb.x, vb.y, vb.z, vb.w };
#pragma unroll
            for (int t = 0; t < 4; t++)
                *(u32*)(sm_ + VHo + off256(e0 + t, cp * 4)) = rnd2h(fa[t], fb[t]);
        }
    }
    // ---- KV' rows 0..63 (rounded) ----
    {
        const float* kvp = g_kv + (size_t)bid * (MM * DD);
        for (int i = tid; i < DD * 16; i += 256) {
            int m = i >> 4, dq = (i & 15) << 2;
            float4 t4 = *(const float4*)(kvp + (size_t)m * DD + dq);
            *(uint2*)(sm_ + WHo + off128(m, dq * 2)) =
                make_uint2(rnd2h(t4.x, t4.y), rnd2h(t4.z, t4.w));
        }
    }
    // ---- KV' row 64 = ksum_prev ----
    if (tid < 16) {
        float4 t4 = *(const float4*)(g_ksum + (size_t)bid * DD + tid * 4);
        *(uint2*)(sm_ + WHo + off128(64, tid * 8)) =
            make_uint2(rnd2h(t4.x, t4.y), rnd2h(t4.z, t4.w));
    }
    // ---- V' rows 64..71 (ones row / zero), KV' rows 65..71 zero ----
    for (int i = tid; i < 512; i += 256) {
        int row = 64 + (i >> 6), cu = i & 63;
        *(u32*)(sm_ + VHo + row * 256 + cu * 4) = (row == 64) ? 0x3C003C00u : 0u;
    }
    if (tid < 224) {
        int row = 65 + (tid >> 5), cu = tid & 31;
        *(u32*)(sm_ + WHo + row * 128 + cu * 4) = 0u;
    }
    __syncthreads();

    const int perm[8] = { 0, 7, 1, 6, 2, 5, 3, 4 };
    int wb = perm[wid];
    int m0 = wb * 16;
    int grp = lane >> 2, tg = lane & 3;
    int rA = m0 + ((lane >> 3) & 1) * 8 + (lane & 7);
    int rB = (lane >> 4) * 8 + (lane & 7);
    int kbA0 = 16 * (lane >> 4);
    int kbB0 = 16 * ((lane >> 3) & 1);
    int r9 = 64 + (lane & 7);
    int r0 = m0 + grp, r1 = r0 + 8;

    // ---- cache Q fragments (shared by GEMM1 and inter) ----
    u32 qh[4][4], ql[4][4];
#pragma unroll
    for (int ks = 0; ks < 4; ks++) {
        ldm4(qh[ks][0], qh[ks][1], qh[ks][2], qh[ks][3], sb + QHo + off128(rA, 32 * ks + kbA0));
        ldm4(ql[ks][0], ql[ks][1], ql[ks][2], ql[ks][3], sb + QLo + off128(rA, 32 * ks + kbA0));
    }

    float accO[9][4] = {};

    // ---- inter: O += Q KV'^T (N=72, z col 64) ----
#pragma unroll
    for (int ks = 0; ks < 4; ks++) {
        int kb = 32 * ks + kbB0;
#pragma unroll
        for (int jb = 0; jb < 4; jb++) {
            u32 b0, b1, b2, b3;
            ldm4(b0, b1, b2, b3, sb + WHo + off128(jb * 16 + rB, kb));
            mma16816(accO[2 * jb],     qh[ks][0], qh[ks][1], qh[ks][2], qh[ks][3], b0, b1);
            mma16816(accO[2 * jb + 1], qh[ks][0], qh[ks][1], qh[ks][2], qh[ks][3], b2, b3);
            mma16816(accO[2 * jb],     ql[ks][0], ql[ks][1], ql[ks][2], ql[ks][3], b0, b1);
            mma16816(accO[2 * jb + 1], ql[ks][0], ql[ks][1], ql[ks][2], ql[ks][3], b2, b3);
        }
        u32 b0, b1;
        ldm2(b0, b1, sb + WHo + off128(r9, kb));
        mma16816(accO[8], qh[ks][0], qh[ks][1], qh[ks][2], qh[ks][3], b0, b1);
        mma16816(accO[8], ql[ks][0], ql[ks][1], ql[ks][2], ql[ks][3], b0, b1);
    }

    // ---- S blocks (jb <= wb): GEMM1 block -> mask -> split -> intra ----
#pragma unroll
    for (int jb = 0; jb < 8; jb++) {
        if (jb <= wb) {
            float s0[4] = {}, s1[4] = {};
#pragma unroll
            for (int ks = 0; ks < 4; ks++) {
                u32 b0, b1, b2, b3;
                ldm4(b0, b1, b2, b3, sb + KHo + off128(jb * 16 + rB, 32 * ks + kbB0));
                mma16816(s0, qh[ks][0], qh[ks][1], qh[ks][2], qh[ks][3], b0, b1);
                mma16816(s1, qh[ks][0], qh[ks][1], qh[ks][2], qh[ks][3], b2, b3);
                mma16816(s0, ql[ks][0], ql[ks][1], ql[ks][2], ql[ks][3], b0, b1);
                mma16816(s1, ql[ks][0], ql[ks][1], ql[ks][2], ql[ks][3], b2, b3);
            }
            // mask tril
            int cA = jb * 16 + tg * 2, cB = cA + 8;
            if (cA > r0)     s0[0] = 0.f;
            if (cA + 1 > r0) s0[1] = 0.f;
            if (cA > r1)     s0[2] = 0.f;
            if (cA + 1 > r1) s0[3] = 0.f;
            if (cB > r0)     s1[0] = 0.f;
            if (cB + 1 > r0) s1[1] = 0.f;
            if (cB > r1)     s1[2] = 0.f;
            if (cB + 1 > r1) s1[3] = 0.f;
            // split S to fp16 A-fragments
            u32 sh0, sh1, sh2, sh3, sl0, sl1, sl2, sl3;
            split2h(s0[0], s0[1], sh0, sl0);
            split2h(s0[2], s0[3], sh1, sl1);
            split2h(s1[0], s1[1], sh2, sl2);
            split2h(s1[2], s1[3], sh3, sl3);
            // intra: O += S_blk V'^T  (k-step = jb)
            int kb2 = 32 * jb + kbB0;
#pragma unroll
            for (int vjb = 0; vjb < 4; vjb++) {
                u32 b0, b1, b2, b3;
                ldm4(b0, b1, b2, b3, sb + VHo + off256(vjb * 16 + rB, kb2));
                mma16816(accO[2 * vjb],     sh0, sh1, sh2, sh3, b0, b1);
                mma16816(accO[2 * vjb + 1], sh0, sh1, sh2, sh3, b2, b3);
                mma16816(accO[2 * vjb],     sl0, sl1, sl2, sl3, b0, b1);
                mma16816(accO[2 * vjb + 1], sl0, sl1, sl2, sl3, b2, b3);
            }
            u32 b0, b1;
            ldm2(b0, b1, sb + VHo + off256(r9, kb2));
            mma16816(accO[8], sh0, sh1, sh2, sh3, b0, b1);
            mma16816(accO[8], sl0, sl1, sl2, sl3, b0, b1);
        }
    }

    // ---- normalize + store ----
    float zr0 = __shfl_sync(0xffffffffu, accO[8][0], lane & 28);
    float zr1 = __shfl_sync(0xffffffffu, accO[8][2], lane & 28);
    float rz0 = 1.0f / (zr0 + EPSF);
    float rz1 = 1.0f / (zr1 + EPSF);
    float* op0 = out + (((size_t)n * LL + (size_t)gc * CC + r0) * HH + h) * MM;
    float* op1 = op0 + (size_t)8 * HH * MM;
#pragma unroll
    for (int j = 0; j < 8; j++) {
        int c0 = j * 8 + tg * 2;
        *(float2*)(op0 + c0) = make_float2(accO[j][0] * rz0, accO[j][1] * rz0);
        *(float2*)(op1 + c0) = make_float2(accO[j][2] * rz1, accO[j][3] * rz1);
    }
}

// ---------------------------------------------------------------------------
extern "C" void kernel_launch(void* const* d_in, const int* in_sizes, int n_in,
                              void* d_out, int out_size)
{
    const float* q = (const float*)d_in[0];
    const float* k = (const float*)d_in[1];
    const float* v = (const float*)d_in[2];
    float* out = (float*)d_out;

    const int SMEM_A = 49152;

    cudaFuncSetAttribute(chunk_state_kernel,
                         cudaFuncAttributeMaxDynamicSharedMemorySize, SMEM_A);
    cudaFuncSetAttribute(output_kernel,
                         cudaFuncAttributeMaxDynamicSharedMemorySize, SMEM_C);

    chunk_state_kernel<<<NN * GG * HH, 256, SMEM_A>>>(k, v);
    prefix_kernel<<<NN * HH * 4, 256>>>();
    output_kernel<<<NN * GG * HH, 256, SMEM_C>>>(q, k, v, out);
}

// round 10
// speedup vs baseline: 1.7970x; 1.0753x over previous
#include <cuda_runtime.h>
#include <cuda_fp16.h>
#include <math.h>
#include <stdint.h>

#define NN 4
#define LL 4096
#define HH 16
#define DD 64
#define MM 64
#define CC 128
#define GG 32
#define EPSF 1e-6f

typedef unsigned int u32;

// Scratch: per-chunk kvT stored as packed fp16 pairs (half2 along d) + fp32 ksum.
static __device__ u32   g_kvh[(size_t)NN * GG * HH * MM * (DD / 2)];   // 16.7MB
static __device__ float g_ksum[(size_t)NN * GG * HH * DD];

__device__ __forceinline__ float phi(float x) { return x > 0.f ? x + 1.f : __expf(x); }

__device__ __forceinline__ void split2h(float x0, float x1, u32& h, u32& l) {
    __half2 hh = __floats2half2_rn(x0, x1);
    float2 f = __half22float2(hh);
    __half2 ll = __floats2half2_rn(x0 - f.x, x1 - f.y);
    h = *reinterpret_cast<u32*>(&hh);
    l = *reinterpret_cast<u32*>(&ll);
}
__device__ __forceinline__ u32 rnd2h(float x0, float x1) {
    __half2 hh = __floats2half2_rn(x0, x1);
    return *reinterpret_cast<u32*>(&hh);
}
__device__ __forceinline__ float2 h2f(u32 u) {
    return __half22float2(*reinterpret_cast<__half2*>(&u));
}

__device__ __forceinline__ u32 smem_u32(const void* p) {
    u32 a;
    asm("{ .reg .u64 t; cvta.to.shared.u64 t, %1; cvt.u32.u64 %0, t; }" : "=r"(a) : "l"(p));
    return a;
}
__device__ __forceinline__ void ldm4(u32& r0, u32& r1, u32& r2, u32& r3, u32 a) {
    asm volatile("ldmatrix.sync.aligned.m8n8.x4.shared.b16 {%0,%1,%2,%3},[%4];"
                 : "=r"(r0), "=r"(r1), "=r"(r2), "=r"(r3) : "r"(a));
}
__device__ __forceinline__ void ldm2(u32& r0, u32& r1, u32 a) {
    asm volatile("ldmatrix.sync.aligned.m8n8.x2.shared.b16 {%0,%1},[%2];"
                 : "=r"(r0), "=r"(r1) : "r"(a));
}
__device__ __forceinline__ void mma16816(float* d, u32 a0, u32 a1, u32 a2, u32 a3,
                                         u32 b0, u32 b1) {
    asm("mma.sync.aligned.m16n8k16.row.col.f32.f16.f16.f32 "
        "{%0,%1,%2,%3},{%4,%5,%6,%7},{%8,%9},{%0,%1,%2,%3};"
        : "+f"(d[0]), "+f"(d[1]), "+f"(d[2]), "+f"(d[3])
        : "r"(a0), "r"(a1), "r"(a2), "r"(a3), "r"(b0), "r"(b1));
}
__device__ __forceinline__ u32 off128(int row, int kb) {
    return (u32)(row * 128) + (u32)(((((kb >> 4) & 7) ^ (row & 7)) << 4) | (kb & 15));
}
__device__ __forceinline__ u32 off256(int row, int kb) {
    return (u32)(row * 256) + (u32)(kb & 128)
         + (u32)(((((kb >> 4) & 7) ^ (row & 7)) << 4) | (kb & 15));
}

// ---------------------------------------------------------------------------
// Kernel A: kvT[m][d] = sum_c v[c][m] * phi(k)[c][d]
// fp16 1-pass V (kv is consumed fp16-rounded anyway), K rounded. smem 32KB.
// ---------------------------------------------------------------------------
__global__ void __launch_bounds__(256, 3) chunk_state_kernel(
    const float* __restrict__ k, const float* __restrict__ v)
{
    extern __shared__ char sm_[];
    const int VTH = 0, KTH = 16384;
    u32 sb = smem_u32(sm_);

    int tid = threadIdx.x, lane = tid & 31, wid = tid >> 5;
    int bid = blockIdx.x;
    int h = bid % HH;
    int gc = (bid / HH) % GG;
    int n = bid / (HH * GG);
    size_t base = (((size_t)n * LL + (size_t)gc * CC) * HH + h) * DD;

    int e0 = (tid & 15) * 4;
#pragma unroll
    for (int it = 0; it < 4; it++) {
        int cp = it * 16 + (tid >> 4);
        size_t off0 = base + (size_t)(cp * 2) * (HH * DD) + e0;
        float4 ka = *(const float4*)(k + off0);
        float4 kb = *(const float4*)(k + off0 + HH * DD);
        float4 va = *(const float4*)(v + off0);
        float4 vb = *(const float4*)(v + off0 + HH * DD);
        float fka[4] = { phi(ka.x), phi(ka.y), phi(ka.z), phi(ka.w) };
        float fkb[4] = { phi(kb.x), phi(kb.y), phi(kb.z), phi(kb.w) };
        float fva[4] = { va.x, va.y, va.z, va.w };
        float fvb[4] = { vb.x, vb.y, vb.z, vb.w };
#pragma unroll
        for (int t = 0; t < 4; t++) {
            u32 ob = off256(e0 + t, cp * 4);
            *(u32*)(sm_ + KTH + ob) = rnd2h(fka[t], fkb[t]);
            *(u32*)(sm_ + VTH + ob) = rnd2h(fva[t], fvb[t]);
        }
    }
    __syncthreads();

    int grp = lane >> 2, tg = lane & 3;
    int m0 = (wid >> 1) * 16, n0 = (wid & 1) * 32;
    int rA = m0 + ((lane >> 3) & 1) * 8 + (lane & 7);
    int rB = (lane >> 4) * 8 + (lane & 7);
    int kbA0 = 16 * (lane >> 4);
    int kbB0 = 16 * ((lane >> 3) & 1);

    float acc[4][4] = {};
#pragma unroll
    for (int ks = 0; ks < 8; ks++) {
        u32 a0, a1, a2, a3;
        ldm4(a0, a1, a2, a3, sb + VTH + off256(rA, 32 * ks + kbA0));
#pragma unroll
        for (int jb = 0; jb < 2; jb++) {
            u32 b0, b1, b2, b3;
            ldm4(b0, b1, b2, b3, sb + KTH + off256(n0 + jb * 16 + rB, 32 * ks + kbB0));
            mma16816(acc[2 * jb],     a0, a1, a2, a3, b0, b1);
            mma16816(acc[2 * jb + 1], a0, a1, a2, a3, b2, b3);
        }
    }

    // packed fp16 write: [m][d/2] u32
    u32* kvout = g_kvh + (size_t)bid * (MM * DD / 2);
#pragma unroll
    for (int j = 0; j < 4; j++) {
        int dc = n0 + (j >> 1) * 16 + (j & 1) * 8 + tg * 2;   // even
        kvout[(size_t)(m0 + grp) * 32 + (dc >> 1)]     = rnd2h(acc[j][0], acc[j][1]);
        kvout[(size_t)(m0 + grp + 8) * 32 + (dc >> 1)] = rnd2h(acc[j][2], acc[j][3]);
    }

    if (tid < DD) {
        float s = 0.f;
#pragma unroll 8
        for (int j = 0; j < 64; j++) {
            int cu = (j + (tid >> 3) * 8) & 63;
            float2 f = h2f(*(const u32*)(sm_ + KTH + off256(tid, cu * 4)));
            s += f.x + f.y;
        }
        g_ksum[(size_t)bid * DD + tid] = s;
    }
}

// ---------------------------------------------------------------------------
// Kernel B: exclusive prefix over chunks (fp16 storage, fp32 accumulation)
// ---------------------------------------------------------------------------
__global__ void __launch_bounds__(256) prefix_kernel()
{
    int nh = blockIdx.x >> 2, qtr = blockIdx.x & 3;
    int n = nh / HH, h = nh % HH;
    int p2 = qtr * 256 + threadIdx.x;                 // uint2 index 0..1023
    float4 run = make_float4(0.f, 0.f, 0.f, 0.f);
    for (int g = 0; g < GG; g++) {
        uint2* p = (uint2*)(g_kvh + (((size_t)(n * GG + g) * HH) + h) * (MM * DD / 2)) + p2;
        uint2 t = *p;
        float2 f0 = h2f(t.x), f1 = h2f(t.y);
        *p = make_uint2(rnd2h(run.x, run.y), rnd2h(run.z, run.w));
        run.x += f0.x; run.y += f0.y; run.z += f1.x; run.w += f1.y;
    }
    if (qtr == 0 && threadIdx.x < DD / 4) {
        float4 rs = make_float4(0.f, 0.f, 0.f, 0.f);
        for (int g = 0; g < GG; g++) {
            float4* p = (float4*)(g_ksum + (((size_t)(n * GG + g) * HH) + h) * DD) + threadIdx.x;
            float4 t = *p;
            *p = rs;
            rs.x += t.x; rs.y += t.y; rs.z += t.z; rs.w += t.w;
        }
    }
}

// ---------------------------------------------------------------------------
// Kernel C: fp16 2-pass (Q/S split, K/V/KV rounded), fused z, triangle skip.
// ---------------------------------------------------------------------------
#define QHo 0
#define QLo 16384
#define KHo 32768
#define VHo 49152
#define WHo 67584
#define SMEM_C 76800

__global__ void __launch_bounds__(256, 2) output_kernel(
    const float* __restrict__ q, const float* __restrict__ k,
    const float* __restrict__ v, float* __restrict__ out)
{
    extern __shared__ char sm_[];
    u32 sb = smem_u32(sm_);

    int tid = threadIdx.x, lane = tid & 31, wid = tid >> 5;
    int bid = blockIdx.x;
    int h = bid % HH;
    int gc = (bid / HH) % GG;
    int n = bid / (HH * GG);
    size_t base = (((size_t)n * LL + (size_t)gc * CC) * HH + h) * DD;

    // ---- Q (split) and K (rounded) rows ----
    for (int i = tid; i < CC * 16; i += 256) {
        int c = i >> 4, dq = (i & 15) << 2;
        size_t off = base + (size_t)c * (HH * DD) + dq;
        float4 q4 = *(const float4*)(q + off);
        float4 k4 = *(const float4*)(k + off);
        u32 ob = off128(c, dq * 2);
        u32 h01, l01, h23, l23;
        split2h(phi(q4.x), phi(q4.y), h01, l01);
        split2h(phi(q4.z), phi(q4.w), h23, l23);
        *(uint2*)(sm_ + QHo + ob) = make_uint2(h01, h23);
        *(uint2*)(sm_ + QLo + ob) = make_uint2(l01, l23);
        *(uint2*)(sm_ + KHo + ob) =
            make_uint2(rnd2h(phi(k4.x), phi(k4.y)), rnd2h(phi(k4.z), phi(k4.w)));
    }
    // ---- V transposed (rounded) rows 0..63 ----
    {
        int e0 = (tid & 15) * 4;
#pragma unroll
        for (int it = 0; it < 4; it++) {
            int cp = it * 16 + (tid >> 4);
            size_t off0 = base + (size_t)(cp * 2) * (HH * DD) + e0;
            float4 va = *(const float4*)(v + off0);
            float4 vb = *(const float4*)(v + off0 + HH * DD);
            float fa[4] = { va.x, va.y, va.z, va.w };
            float fb[4] = { vb.x, vb.y, vb.z, vb.w };
#pragma unroll
            for (int t = 0; t < 4; t++)
                *(u32*)(sm_ + VHo + off256(e0 + t, cp * 4)) = rnd2h(fa[t], fb[t]);
        }
    }
    // ---- KV' rows 0..63: straight fp16 copy (1024 uint2 = full 8KB plane) ----
    {
        const u32* kvp = g_kvh + (size_t)bid * (MM * DD / 2);
        for (int i = tid; i < 1024; i += 256) {
            int m = i >> 4, du = (i & 15) * 2;        // u32 index within row
            uint2 t = *(const uint2*)(kvp + (size_t)m * 32 + du);
            *(uint2*)(sm_ + WHo + off128(m, du * 4)) = t;
        }
    }
    // ---- KV' row 64 = ksum_prev ----
    if (tid < 16) {
        float4 t4 = *(const float4*)(g_ksum + (size_t)bid * DD + tid * 4);
        *(uint2*)(sm_ + WHo + off128(64, tid * 8)) =
            make_uint2(rnd2h(t4.x, t4.y), rnd2h(t4.z, t4.w));
    }
    // ---- V' rows 64..71 (ones / zero), KV' rows 65..71 zero ----
    for (int i = tid; i < 512; i += 256) {
        int row = 64 + (i >> 6), cu = i & 63;
        *(u32*)(sm_ + VHo + row * 256 + cu * 4) = (row == 64) ? 0x3C003C00u : 0u;
    }
    if (tid < 224) {
        int row = 65 + (tid >> 5), cu = tid & 31;
        *(u32*)(sm_ + WHo + row * 128 + cu * 4) = 0u;
    }
    __syncthreads();

    const int perm[8] = { 0, 7, 1, 6, 2, 5, 3, 4 };
    int wb = perm[wid];
    int m0 = wb * 16;
    int grp = lane >> 2, tg = lane & 3;
    int rA = m0 + ((lane >> 3) & 1) * 8 + (lane & 7);
    int rB = (lane >> 4) * 8 + (lane & 7);
    int kbA0 = 16 * (lane >> 4);
    int kbB0 = 16 * ((lane >> 3) & 1);
    int r9 = 64 + (lane & 7);
    int r0 = m0 + grp, r1 = r0 + 8;

    // ---- cache Q fragments ----
    u32 qh[4][4], ql[4][4];
#pragma unroll
    for (int ks = 0; ks < 4; ks++) {
        ldm4(qh[ks][0], qh[ks][1], qh[ks][2], qh[ks][3], sb + QHo + off128(rA, 32 * ks + kbA0));
        ldm4(ql[ks][0], ql[ks][1], ql[ks][2], ql[ks][3], sb + QLo + off128(rA, 32 * ks + kbA0));
    }

    float accO[9][4] = {};

    // ---- inter: O += Q KV'^T (N=72, z col 64) ----
#pragma unroll
    for (int ks = 0; ks < 4; ks++) {
        int kb = 32 * ks + kbB0;
#pragma unroll
        for (int jb = 0; jb < 4; jb++) {
            u32 b0, b1, b2, b3;
            ldm4(b0, b1, b2, b3, sb + WHo + off128(jb * 16 + rB, kb));
            mma16816(accO[2 * jb],     qh[ks][0], qh[ks][1], qh[ks][2], qh[ks][3], b0, b1);
            mma16816(accO[2 * jb + 1], qh[ks][0], qh[ks][1], qh[ks][2], qh[ks][3], b2, b3);
            mma16816(accO[2 * jb],     ql[ks][0], ql[ks][1], ql[ks][2], ql[ks][3], b0, b1);
            mma16816(accO[2 * jb + 1], ql[ks][0], ql[ks][1], ql[ks][2], ql[ks][3], b2, b3);
        }
        u32 b0, b1;
        ldm2(b0, b1, sb + WHo + off128(r9, kb));
        mma16816(accO[8], qh[ks][0], qh[ks][1], qh[ks][2], qh[ks][3], b0, b1);
        mma16816(accO[8], ql[ks][0], ql[ks][1], ql[ks][2], ql[ks][3], b0, b1);
    }

    // ---- S blocks (jb <= wb): GEMM1 block -> mask -> split -> intra ----
#pragma unroll
    for (int jb = 0; jb < 8; jb++) {
        if (jb <= wb) {
            float s0[4] = {}, s1[4] = {};
#pragma unroll
            for (int ks = 0; ks < 4; ks++) {
                u32 b0, b1, b2, b3;
                ldm4(b0, b1, b2, b3, sb + KHo + off128(jb * 16 + rB, 32 * ks + kbB0));
                mma16816(s0, qh[ks][0], qh[ks][1], qh[ks][2], qh[ks][3], b0, b1);
                mma16816(s1, qh[ks][0], qh[ks][1], qh[ks][2], qh[ks][3], b2, b3);
                mma16816(s0, ql[ks][0], ql[ks][1], ql[ks][2], ql[ks][3], b0, b1);
                mma16816(s1, ql[ks][0], ql[ks][1], ql[ks][2], ql[ks][3], b2, b3);
            }
            int cA = jb * 16 + tg * 2, cB = cA + 8;
            if (cA > r0)     s0[0] = 0.f;
            if (cA + 1 > r0) s0[1] = 0.f;
            if (cA > r1)     s0[2] = 0.f;
            if (cA + 1 > r1) s0[3] = 0.f;
            if (cB > r0)     s1[0] = 0.f;
            if (cB + 1 > r0) s1[1] = 0.f;
            if (cB > r1)     s1[2] = 0.f;
            if (cB + 1 > r1) s1[3] = 0.f;
            u32 sh0, sh1, sh2, sh3, sl0, sl1, sl2, sl3;
            split2h(s0[0], s0[1], sh0, sl0);
            split2h(s0[2], s0[3], sh1, sl1);
            split2h(s1[0], s1[1], sh2, sl2);
            split2h(s1[2], s1[3], sh3, sl3);
            int kb2 = 32 * jb + kbB0;
#pragma unroll
            for (int vjb = 0; vjb < 4; vjb++) {
                u32 b0, b1, b2, b3;
                ldm4(b0, b1, b2, b3, sb + VHo + off256(vjb * 16 + rB, kb2));
                mma16816(accO[2 * vjb],     sh0, sh1, sh2, sh3, b0, b1);
                mma16816(accO[2 * vjb + 1], sh0, sh1, sh2, sh3, b2, b3);
                mma16816(accO[2 * vjb],     sl0, sl1, sl2, sl3, b0, b1);
                mma16816(accO[2 * vjb + 1], sl0, sl1, sl2, sl3, b2, b3);
            }
            u32 b0, b1;
            ldm2(b0, b1, sb + VHo + off256(r9, kb2));
            mma16816(accO[8], sh0, sh1, sh2, sh3, b0, b1);
            mma16816(accO[8], sl0, sl1, sl2, sl3, b0, b1);
        }
    }

    // ---- normalize + store ----
    float zr0 = __shfl_sync(0xffffffffu, accO[8][0], lane & 28);
    float zr1 = __shfl_sync(0xffffffffu, accO[8][2], lane & 28);
    float rz0 = 1.0f / (zr0 + EPSF);
    float rz1 = 1.0f / (zr1 + EPSF);
    float* op0 = out + (((size_t)n * LL + (size_t)gc * CC + r0) * HH + h) * MM;
    float* op1 = op0 + (size_t)8 * HH * MM;
#pragma unroll
    for (int j = 0; j < 8; j++) {
        int c0 = j * 8 + tg * 2;
        *(float2*)(op0 + c0) = make_float2(accO[j][0] * rz0, accO[j][1] * rz0);
        *(float2*)(op1 + c0) = make_float2(accO[j][2] * rz1, accO[j][3] * rz1);
    }
}

// ---------------------------------------------------------------------------
extern "C" void kernel_launch(void* const* d_in, const int* in_sizes, int n_in,
                              void* d_out, int out_size)
{
    const float* q = (const float*)d_in[0];
    const float* k = (const float*)d_in[1];
    const float* v = (const float*)d_in[2];
    float* out = (float*)d_out;

    const int SMEM_A = 32768;

    cudaFuncSetAttribute(chunk_state_kernel,
                         cudaFuncAttributeMaxDynamicSharedMemorySize, SMEM_A);
    cudaFuncSetAttribute(output_kernel,
                         cudaFuncAttributeMaxDynamicSharedMemorySize, SMEM_C);

    chunk_state_kernel<<<NN * GG * HH, 256, SMEM_A>>>(k, v);
    prefix_kernel<<<NN * HH * 4, 256>>>();
    output_kernel<<<NN * GG * HH, 256, SMEM_C>>>(q, k, v, out);
}